// round 1
// baseline (speedup 1.0000x reference)
#include <cuda_runtime.h>
#include <math.h>

#define BB 4
#define CC 64
#define HH 128
#define WW 128
#define OO 64
#define NKK 9
#define QDIM 576            // C*KK
#define SPITCH 33           // shared pitch for s[q][pix], conflict-free
#define PIXB 32             // pixels per block in main kernel
#define NPAIR (PIXB*NKK)    // 288

// ---- device scratch (static allocation only; no cudaMalloc allowed) ----
__device__ float g_xT[BB*HH*WW*CC];      // NHWC transpose of x   (16.8 MB)
__device__ float g_wT[QDIM*OO];          // wT[kk*64+c][o]
__device__ float g_params[BB*HH*WW*27];  // conv output, [pixel][27]

// ============================================================
// Kernel 0: x NCHW -> NHWC (shared-tile transpose)
// ============================================================
__global__ void k_transpose_x(const float* __restrict__ x) {
    __shared__ float tile[64][129];
    int bh = blockIdx.x;            // 0..511  (b*H + h)
    int b = bh / HH, h = bh % HH;
    int t = threadIdx.x;            // 256 threads
    for (int i = t; i < 64 * 128; i += 256) {
        int c = i >> 7, w = i & 127;
        tile[c][w] = x[((size_t)(b * CC + c) * HH + h) * WW + w];
    }
    __syncthreads();
    for (int i = t; i < 64 * 128; i += 256) {
        int w = i >> 6, c = i & 63;
        g_xT[((size_t)bh * WW + w) * CC + c] = tile[c][w];
    }
}

// ============================================================
// Kernel 1: weight (O,C,3,3) -> wT[(kk*64+c)*64 + o]
// ============================================================
__global__ void k_transpose_w(const float* __restrict__ wgt) {
    int i = blockIdx.x * 256 + threadIdx.x;
    if (i >= OO * CC * NKK) return;
    int o = i / (CC * NKK);
    int r = i % (CC * NKK);
    int c = r / NKK;
    int kk = r % NKK;
    g_wT[(kk * 64 + c) * OO + o] = wgt[i];
}

// ============================================================
// Kernel 2: offset/mask 3x3 conv (Cin=64 -> Cout=27, pad 1)
// one thread per output pixel, all 27 channels in registers
// ============================================================
__global__ void k_params(const float* __restrict__ x,
                         const float* __restrict__ pgw,
                         const float* __restrict__ pgb) {
    extern __shared__ float smem[];
    float* sw = smem;               // 27*576
    float* sb = smem + 27 * QDIM;   // 27
    int bh = blockIdx.x;            // b*H + h
    int b = bh / HH, h = bh % HH;
    int t = threadIdx.x;            // 128 threads, one per w
    for (int i = t; i < 27 * QDIM; i += 128) sw[i] = pgw[i];
    if (t < 27) sb[t] = pgb[t];
    __syncthreads();

    int w = t;
    float acc[27];
#pragma unroll
    for (int co = 0; co < 27; co++) acc[co] = sb[co];

    for (int c = 0; c < CC; c++) {
        float xv[9];
#pragma unroll
        for (int kh = 0; kh < 3; kh++) {
#pragma unroll
            for (int kw = 0; kw < 3; kw++) {
                int hh = h + kh - 1, ww = w + kw - 1;
                float v = 0.f;
                if (hh >= 0 && hh < HH && ww >= 0 && ww < WW)
                    v = __ldg(&x[((size_t)(b * CC + c) * HH + hh) * WW + ww]);
                xv[kh * 3 + kw] = v;
            }
        }
        const float* swc = &sw[c * 9];
#pragma unroll
        for (int co = 0; co < 27; co++) {
#pragma unroll
            for (int k2 = 0; k2 < 9; k2++)
                acc[co] += xv[k2] * swc[co * QDIM + k2];
        }
    }
    float* p = &g_params[((size_t)bh * WW + w) * 27];
#pragma unroll
    for (int co = 0; co < 27; co++) p[co] = acc[co];
}

// ============================================================
// Kernel 3: fused bilinear gather + reduction GEMM
// block: 32 pixels (one row segment), 256 threads
// ============================================================
__global__ void k_main(const float* __restrict__ bias,
                       float* __restrict__ out) {
    extern __shared__ float sm[];
    float* s = sm;                          // [576][33]
    float* pw = sm + QDIM * SPITCH;         // [4][288] corner weights (mask-scaled, validity-zeroed)
    int*   pi = (int*)(pw + 4 * NPAIR);     // [4][288] clamped y0c,y1c,x0c,x1c

    int t = threadIdx.x;
    int blk = blockIdx.x;                   // 2048 = 4*128*4
    int wb = (blk & 3) * PIXB;
    int bh = blk >> 2;                      // b*H + h
    int b = bh / HH, h = bh % HH;

    // ---- phase A: per-(pixel,tap) sampling parameters ----
    for (int pair = t; pair < NPAIR; pair += 256) {
        int kk  = pair >> 5;                // pair = kk*32 + pix
        int pix = pair & 31;
        int w = wb + pix;
        const float* pp = &g_params[((size_t)bh * WW + w) * 27];
        float dy = pp[2 * kk];
        float dx = pp[2 * kk + 1];
        float m  = pp[18 + kk];
        float mask = 1.f / (1.f + expf(-m));
        float ys = (float)(h - 1 + kk / 3) + dy;
        float xs = (float)(w - 1 + kk % 3) + dx;
        float y0f = floorf(ys), x0f = floorf(xs);
        float ly = ys - y0f, lx = xs - x0f;
        int y0 = (int)y0f, x0 = (int)x0f;
        float vy0 = (y0 >= 0 && y0 < HH) ? 1.f : 0.f;
        float vy1 = (y0 + 1 >= 0 && y0 + 1 < HH) ? 1.f : 0.f;
        float vx0 = (x0 >= 0 && x0 < WW) ? 1.f : 0.f;
        float vx1 = (x0 + 1 >= 0 && x0 + 1 < WW) ? 1.f : 0.f;
        pw[0 * NPAIR + pair] = (1.f - ly) * (1.f - lx) * mask * vy0 * vx0;
        pw[1 * NPAIR + pair] = (1.f - ly) * lx         * mask * vy0 * vx1;
        pw[2 * NPAIR + pair] = ly * (1.f - lx)         * mask * vy1 * vx0;
        pw[3 * NPAIR + pair] = ly * lx                 * mask * vy1 * vx1;
        pi[0 * NPAIR + pair] = min(max(y0, 0), HH - 1);
        pi[1 * NPAIR + pair] = min(max(y0 + 1, 0), HH - 1);
        pi[2 * NPAIR + pair] = min(max(x0, 0), WW - 1);
        pi[3 * NPAIR + pair] = min(max(x0 + 1, 0), WW - 1);
    }
    __syncthreads();

    // ---- phase B: bilinear gather into shared s[q][pix] ----
    const float* xb = &g_xT[(size_t)b * HH * WW * CC];
#pragma unroll 2
    for (int i = 0; i < (NPAIR * 64) / 256; i++) {      // 72 iters
        int idx  = i * 256 + t;
        int pair = idx >> 6;
        int c    = idx & 63;
        int kk   = pair >> 5, pix = pair & 31;
        int y0c = pi[0 * NPAIR + pair];
        int y1c = pi[1 * NPAIR + pair];
        int x0c = pi[2 * NPAIR + pair];
        int x1c = pi[3 * NPAIR + pair];
        float w00 = pw[0 * NPAIR + pair];
        float w01 = pw[1 * NPAIR + pair];
        float w10 = pw[2 * NPAIR + pair];
        float w11 = pw[3 * NPAIR + pair];
        int r0 = y0c * WW, r1 = y1c * WW;
        float v;
        v  = w00 * __ldg(&xb[(size_t)(r0 + x0c) * CC + c]);
        v += w01 * __ldg(&xb[(size_t)(r0 + x1c) * CC + c]);
        v += w10 * __ldg(&xb[(size_t)(r1 + x0c) * CC + c]);
        v += w11 * __ldg(&xb[(size_t)(r1 + x1c) * CC + c]);
        s[(kk * 64 + c) * SPITCH + pix] = v;
    }
    __syncthreads();

    // ---- phase C: GEMM  out[pix][o] = sum_q s[q][pix] * wT[q][o] ----
    int og = t & 15;        // o-group: o = og*4 .. og*4+3
    int pg = t >> 4;        // pixel group: pixels pg*2, pg*2+1
    const float4* w4 = (const float4*)g_wT;
    float4 bv = ((const float4*)bias)[og];
    float a00 = bv.x, a01 = bv.x;
    float a10 = bv.y, a11 = bv.y;
    float a20 = bv.z, a21 = bv.z;
    float a30 = bv.w, a31 = bv.w;
    const float* srow = &s[pg * 2];
#pragma unroll 8
    for (int q = 0; q < QDIM; q++) {
        float4 wv = __ldg(&w4[q * 16 + og]);
        float s0 = srow[q * SPITCH];
        float s1 = srow[q * SPITCH + 1];
        a00 += wv.x * s0; a01 += wv.x * s1;
        a10 += wv.y * s0; a11 += wv.y * s1;
        a20 += wv.z * s0; a21 += wv.z * s1;
        a30 += wv.w * s0; a31 += wv.w * s1;
    }
    int w0 = wb + pg * 2;
    int obase = og * 4;
    size_t outb = ((size_t)(b * OO + obase) * HH + h) * WW + w0;
    size_t ostride = (size_t)HH * WW;
    out[outb]               = a00; out[outb + 1]               = a01;
    out[outb + ostride]     = a10; out[outb + ostride + 1]     = a11;
    out[outb + 2 * ostride] = a20; out[outb + 2 * ostride + 1] = a21;
    out[outb + 3 * ostride] = a30; out[outb + 3 * ostride + 1] = a31;
}

// ============================================================
extern "C" void kernel_launch(void* const* d_in, const int* in_sizes, int n_in,
                              void* d_out, int out_size) {
    const float* x      = (const float*)d_in[0];
    const float* weight = (const float*)d_in[1];
    const float* bias   = (const float*)d_in[2];
    const float* pg_w   = (const float*)d_in[3];
    const float* pg_b   = (const float*)d_in[4];
    float* out = (float*)d_out;

    const int SMEM_PARAMS = (27 * QDIM + 32) * 4;                    // ~62.3 KB
    const int SMEM_MAIN   = (QDIM * SPITCH + 8 * NPAIR) * 4;         // ~85.2 KB

    cudaFuncSetAttribute(k_params, cudaFuncAttributeMaxDynamicSharedMemorySize, SMEM_PARAMS);
    cudaFuncSetAttribute(k_main,   cudaFuncAttributeMaxDynamicSharedMemorySize, SMEM_MAIN);

    k_transpose_x<<<BB * HH, 256>>>(x);
    k_transpose_w<<<(OO * CC * NKK + 255) / 256, 256>>>(weight);
    k_params<<<BB * HH, 128, SMEM_PARAMS>>>(x, pg_w, pg_b);
    k_main<<<BB * HH * (WW / PIXB), 256, SMEM_MAIN>>>(bias, out);
}

// round 2
// speedup vs baseline: 1.2980x; 1.2980x over previous
#include <cuda_runtime.h>
#include <math.h>

#define BB 4
#define CC 64
#define HH 128
#define WW 128
#define OO 64
#define NKK 9
#define QDIM 576            // C*KK
#define PIXB 64             // pixels per block (half row)
#define NPAIR (PIXB*NKK)    // 576 pairs per block
#define SP 65               // staging pitch (conflict-free for c-strided stores)

// ---- device scratch ----
__device__ float g_xT[BB*HH*WW*CC];      // NHWC transpose of x
__device__ float g_wT[QDIM*OO];          // wT[kk*64+c][o]
__device__ float g_wpg[QDIM*32];         // offset-conv weights, [q][co padded to 32]
__device__ float g_params[BB*HH*WW*27];  // offset/mask conv output, [pixel][27]

// ============================================================
// Kernel 0: x NCHW -> NHWC
// ============================================================
__global__ void k_transpose_x(const float* __restrict__ x) {
    __shared__ float tile[64][129];
    int bh = blockIdx.x;
    int b = bh >> 7, h = bh & 127;
    int t = threadIdx.x;
    for (int i = t; i < 64 * 128; i += 256) {
        int c = i >> 7, w = i & 127;
        tile[c][w] = x[((size_t)(b * CC + c) * HH + h) * WW + w];
    }
    __syncthreads();
    for (int i = t; i < 64 * 128; i += 256) {
        int w = i >> 6, c = i & 63;
        g_xT[((size_t)bh * WW + w) * CC + c] = tile[c][w];
    }
}

// ============================================================
// Kernel 1: weight (O,C,3,3) -> wT[(kk*64+c)*64 + o]
// ============================================================
__global__ void k_transpose_w(const float* __restrict__ wgt) {
    int i = blockIdx.x * 256 + threadIdx.x;
    if (i >= OO * CC * NKK) return;
    int o = i / (CC * NKK);
    int r = i % (CC * NKK);
    int c = r / NKK;
    int kk = r % NKK;
    g_wT[(kk * 64 + c) * OO + o] = wgt[i];
}

// ============================================================
// Kernel 1b: pg_w (27,C,3,3) -> wpg[q=c*9+k][co padded 32]
// ============================================================
__global__ void k_prep_wpg(const float* __restrict__ pgw) {
    int i = blockIdx.x * 256 + threadIdx.x;   // 576*32
    if (i >= QDIM * 32) return;
    int q = i >> 5;
    int co = i & 31;
    g_wpg[i] = (co < 27) ? pgw[co * QDIM + q] : 0.f;
}

// ============================================================
// Kernel 2: offset/mask 3x3 conv as chunked implicit GEMM
// block = 64 pixels (half row), 256 threads
// out[pix][27] = sum_q patch[q][pix] * wpg[q][co]
// ============================================================
__global__ void k_params(const float* __restrict__ x,
                         const float* __restrict__ pgb) {
    __shared__ float s2[72 * SP];
    int t = threadIdx.x;
    int blk = blockIdx.x;                 // 1024
    int wb = (blk & 1) * PIXB;
    int bh = blk >> 1;
    int b = bh >> 7, h = bh & 127;

    int og = t & 7;                       // co = og*4 .. og*4+3
    int pg = t >> 3;                      // pixels pg*2, pg*2+1
    float a00, a01, a10, a11, a20, a21, a30, a31;
    {
        int c0 = og * 4;
        float b0 = (c0 + 0 < 27) ? __ldg(&pgb[c0 + 0]) : 0.f;
        float b1 = (c0 + 1 < 27) ? __ldg(&pgb[c0 + 1]) : 0.f;
        float b2 = (c0 + 2 < 27) ? __ldg(&pgb[c0 + 2]) : 0.f;
        float b3 = (c0 + 3 < 27) ? __ldg(&pgb[c0 + 3]) : 0.f;
        a00 = b0; a01 = b0; a10 = b1; a11 = b1;
        a20 = b2; a21 = b2; a30 = b3; a31 = b3;
    }
    const float4* w4 = (const float4*)g_wpg;   // [q][8 groups of 4co]
    const float* srow = &s2[pg * 2];

    for (int cb = 0; cb < 8; cb++) {           // 8 channels per chunk
        __syncthreads();
        // stage patch: 72 q x 64 pix
#pragma unroll
        for (int it = 0; it < 18; it++) {
            int idx = it * 256 + t;
            int ql = idx >> 6;                 // 0..71
            int pix = idx & 63;
            int c = cb * 8 + ql / 9;
            int k2 = ql % 9;
            int hh = h + k2 / 3 - 1;
            int ww = wb + pix + k2 % 3 - 1;
            float v = 0.f;
            if (hh >= 0 && hh < HH && ww >= 0 && ww < WW)
                v = __ldg(&x[((size_t)(b * CC + c) * HH + hh) * WW + ww]);
            s2[ql * SP + pix] = v;
        }
        __syncthreads();
#pragma unroll 9
        for (int ql = 0; ql < 72; ql++) {
            float4 wv = __ldg(&w4[(cb * 72 + ql) * 8 + og]);
            float s0 = srow[ql * SP];
            float s1 = srow[ql * SP + 1];
            a00 += wv.x * s0; a01 += wv.x * s1;
            a10 += wv.y * s0; a11 += wv.y * s1;
            a20 += wv.z * s0; a21 += wv.z * s1;
            a30 += wv.w * s0; a31 += wv.w * s1;
        }
    }
    int w0 = wb + pg * 2;
    int c0 = og * 4;
    float* p0 = &g_params[((size_t)bh * WW + w0) * 27];
    float* p1 = p0 + 27;
    if (c0 + 0 < 27) { p0[c0 + 0] = a00; p1[c0 + 0] = a01; }
    if (c0 + 1 < 27) { p0[c0 + 1] = a10; p1[c0 + 1] = a11; }
    if (c0 + 2 < 27) { p0[c0 + 2] = a20; p1[c0 + 2] = a21; }
    if (c0 + 3 < 27) { p0[c0 + 3] = a30; p1[c0 + 3] = a31; }
}

// ============================================================
// Kernel 3: fused bilinear gather + GEMM, chunked over taps
// block = 64 pixels, 256 threads, 9 chunks of 64 channels
// ============================================================
__global__ void k_main(const float* __restrict__ bias,
                       float* __restrict__ out) {
    extern __shared__ float sm[];
    float* s  = sm;                      // [64][SP]
    float* pw = sm + 64 * SP;            // [4][576]
    int*   pi = (int*)(pw + 4 * NPAIR);  // [4][576]

    int t = threadIdx.x;
    int blk = blockIdx.x;                // 1024
    int wb = (blk & 1) * PIXB;
    int bh = blk >> 1;
    int b = bh >> 7, h = bh & 127;

    // ---- phase A: per-(pixel,tap) sampling parameters ----
    for (int pair = t; pair < NPAIR; pair += 256) {
        int kk  = pair >> 6;
        int pix = pair & 63;
        int w = wb + pix;
        const float* pp = &g_params[((size_t)bh * WW + w) * 27];
        float dy = pp[2 * kk];
        float dx = pp[2 * kk + 1];
        float m  = pp[18 + kk];
        float mask = 1.f / (1.f + expf(-m));
        float ys = (float)(h - 1 + kk / 3) + dy;
        float xs = (float)(w - 1 + kk % 3) + dx;
        float y0f = floorf(ys), x0f = floorf(xs);
        float ly = ys - y0f, lx = xs - x0f;
        int y0 = (int)y0f, x0 = (int)x0f;
        float vy0 = (y0 >= 0 && y0 < HH) ? 1.f : 0.f;
        float vy1 = (y0 + 1 >= 0 && y0 + 1 < HH) ? 1.f : 0.f;
        float vx0 = (x0 >= 0 && x0 < WW) ? 1.f : 0.f;
        float vx1 = (x0 + 1 >= 0 && x0 + 1 < WW) ? 1.f : 0.f;
        pw[0 * NPAIR + pair] = (1.f - ly) * (1.f - lx) * mask * vy0 * vx0;
        pw[1 * NPAIR + pair] = (1.f - ly) * lx         * mask * vy0 * vx1;
        pw[2 * NPAIR + pair] = ly * (1.f - lx)         * mask * vy1 * vx0;
        pw[3 * NPAIR + pair] = ly * lx                 * mask * vy1 * vx1;
        pi[0 * NPAIR + pair] = min(max(y0, 0), HH - 1) * WW;
        pi[1 * NPAIR + pair] = min(max(y0 + 1, 0), HH - 1) * WW;
        pi[2 * NPAIR + pair] = min(max(x0, 0), WW - 1);
        pi[3 * NPAIR + pair] = min(max(x0 + 1, 0), WW - 1);
    }

    int og = t & 15;                     // o = og*4..og*4+3
    int pg = t >> 4;                     // pixels pg*4..pg*4+3
    float acc[16];                       // acc[p*4+o]
    {
        float4 bv = __ldg(&((const float4*)bias)[og]);
#pragma unroll
        for (int p = 0; p < 4; p++) {
            acc[p * 4 + 0] = bv.x; acc[p * 4 + 1] = bv.y;
            acc[p * 4 + 2] = bv.z; acc[p * 4 + 3] = bv.w;
        }
    }
    const float4* w4 = (const float4*)g_wT;
    const float* srow = &s[pg * 4];
    const float* xb = &g_xT[(size_t)b * HH * WW * CC];

    for (int kk = 0; kk < NKK; kk++) {
        __syncthreads();
        // ---- gather chunk: 64 c x 64 pix ----
#pragma unroll
        for (int it = 0; it < 16; it++) {
            int idx = it * 256 + t;
            int pix = idx >> 6;
            int c   = idx & 63;
            int pair = kk * 64 + pix;
            int r0 = pi[0 * NPAIR + pair];
            int r1 = pi[1 * NPAIR + pair];
            int x0c = pi[2 * NPAIR + pair];
            int x1c = pi[3 * NPAIR + pair];
            float w00 = pw[0 * NPAIR + pair];
            float w01 = pw[1 * NPAIR + pair];
            float w10 = pw[2 * NPAIR + pair];
            float w11 = pw[3 * NPAIR + pair];
            float v;
            v  = w00 * __ldg(&xb[(size_t)(r0 + x0c) * CC + c]);
            v += w01 * __ldg(&xb[(size_t)(r0 + x1c) * CC + c]);
            v += w10 * __ldg(&xb[(size_t)(r1 + x0c) * CC + c]);
            v += w11 * __ldg(&xb[(size_t)(r1 + x1c) * CC + c]);
            s[c * SP + pix] = v;
        }
        __syncthreads();
        // ---- GEMM chunk: 64 q ----
#pragma unroll 8
        for (int ql = 0; ql < 64; ql++) {
            float4 wv = __ldg(&w4[(kk * 64 + ql) * 16 + og]);
            float s0 = srow[ql * SP];
            float s1 = srow[ql * SP + 1];
            float s2v = srow[ql * SP + 2];
            float s3 = srow[ql * SP + 3];
            acc[0]  += wv.x * s0;  acc[1]  += wv.y * s0;
            acc[2]  += wv.z * s0;  acc[3]  += wv.w * s0;
            acc[4]  += wv.x * s1;  acc[5]  += wv.y * s1;
            acc[6]  += wv.z * s1;  acc[7]  += wv.w * s1;
            acc[8]  += wv.x * s2v; acc[9]  += wv.y * s2v;
            acc[10] += wv.z * s2v; acc[11] += wv.w * s2v;
            acc[12] += wv.x * s3;  acc[13] += wv.y * s3;
            acc[14] += wv.z * s3;  acc[15] += wv.w * s3;
        }
    }

    // ---- store: 4 o-planes x 4 consecutive w (float4 each) ----
    int w0 = wb + pg * 4;
    size_t base = ((size_t)(b * OO + og * 4) * HH + h) * WW + w0;
    size_t ostride = (size_t)HH * WW;
#pragma unroll
    for (int i = 0; i < 4; i++) {
        float4 v;
        v.x = acc[0 * 4 + i]; v.y = acc[1 * 4 + i];
        v.z = acc[2 * 4 + i]; v.w = acc[3 * 4 + i];
        *(float4*)&out[base + i * ostride] = v;
    }
}

// ============================================================
extern "C" void kernel_launch(void* const* d_in, const int* in_sizes, int n_in,
                              void* d_out, int out_size) {
    const float* x      = (const float*)d_in[0];
    const float* weight = (const float*)d_in[1];
    const float* bias   = (const float*)d_in[2];
    const float* pg_w   = (const float*)d_in[3];
    const float* pg_b   = (const float*)d_in[4];
    float* out = (float*)d_out;

    const int SMEM_MAIN = (64 * SP + 8 * NPAIR) * 4;   // ~35 KB

    cudaFuncSetAttribute(k_main, cudaFuncAttributeMaxDynamicSharedMemorySize, SMEM_MAIN);

    k_transpose_x<<<BB * HH, 256>>>(x);
    k_transpose_w<<<(OO * CC * NKK + 255) / 256, 256>>>(weight);
    k_prep_wpg<<<(QDIM * 32 + 255) / 256, 256>>>(pg_w);
    k_params<<<BB * HH * (WW / PIXB), 256>>>(x, pg_b);
    k_main<<<BB * HH * (WW / PIXB), 256, SMEM_MAIN>>>(bias, out);
}

// round 3
// speedup vs baseline: 2.3489x; 1.8097x over previous
#include <cuda_runtime.h>
#include <math.h>

#define BB 4
#define CC 64
#define HH 128
#define WW 128
#define OO 64
#define NKK 9
#define QDIM 576
#define PIXB 64
#define NPAIR (PIXB*NKK)    // 576
#define SP 65               // k_main staging pitch (scalar, odd -> conflict-free)
#define SPP 68              // k_params patch pitch (float4-aligned, conflict-free reads)

// ---- device scratch ----
__device__ float g_xT[BB*HH*WW*CC];        // NHWC transpose of x
__device__ float g_wT[QDIM*OO];            // wT[kk*64+c][o]
__device__ float g_wpg2[NKK*CC*32];        // pg weights [kk][c][co padded 32]
__device__ float g_params[BB*HH*WW*27];    // offset/mask conv out, [pixel][27]

// ============================================================
// Kernel 0: x NCHW -> NHWC
// ============================================================
__global__ void k_transpose_x(const float* __restrict__ x) {
    __shared__ float tile[64][129];
    int bh = blockIdx.x;
    int b = bh >> 7, h = bh & 127;
    int t = threadIdx.x;
    for (int i = t; i < 64 * 128; i += 256) {
        int c = i >> 7, w = i & 127;
        tile[c][w] = x[((size_t)(b * CC + c) * HH + h) * WW + w];
    }
    __syncthreads();
    for (int i = t; i < 64 * 128; i += 256) {
        int w = i >> 6, c = i & 63;
        g_xT[((size_t)bh * WW + w) * CC + c] = tile[c][w];
    }
}

// ============================================================
// Kernel 1: weight (O,C,3,3) -> wT[(kk*64+c)*64 + o]
// ============================================================
__global__ void k_transpose_w(const float* __restrict__ wgt) {
    int i = blockIdx.x * 256 + threadIdx.x;
    if (i >= OO * CC * NKK) return;
    int o = i / (CC * NKK);
    int r = i % (CC * NKK);
    int c = r / NKK;
    int kk = r % NKK;
    g_wT[(kk * 64 + c) * OO + o] = wgt[i];
}

// ============================================================
// Kernel 1b: pg_w (27,C,3,3) -> wpg2[kk][c][co32]
// ============================================================
__global__ void k_prep_wpg2(const float* __restrict__ pgw) {
    int i = blockIdx.x * 256 + threadIdx.x;     // 9*64*32 = 18432
    if (i >= NKK * CC * 32) return;
    int co = i & 31;
    int c  = (i >> 5) & 63;
    int kk = i >> 11;
    g_wpg2[i] = (co < 27) ? pgw[co * QDIM + c * 9 + kk] : 0.f;
}

// ============================================================
// Kernel 2: offset/mask conv as 9 per-tap GEMMs over g_xT
// block = 64 px, 256 threads; thread tile 4co x 2px
// ============================================================
__global__ void k_params(const float* __restrict__ pgb) {
    __shared__ float sp[64 * SPP];     // patch [pix][c], pitch 68
    __shared__ float swp[64 * 32];     // weights [c][co32]
    int t = threadIdx.x;
    int blk = blockIdx.x;              // 1024
    int wb = (blk & 1) * PIXB;
    int bh = blk >> 1;
    int b = bh >> 7, h = bh & 127;

    int og = t & 7;                    // co = og*4..og*4+3
    int pg = t >> 3;                   // pixels pg*2, pg*2+1
    float a00, a01, a10, a11, a20, a21, a30, a31;
    {
        int c0 = og * 4;
        float b0 = (c0 + 0 < 27) ? __ldg(&pgb[c0 + 0]) : 0.f;
        float b1 = (c0 + 1 < 27) ? __ldg(&pgb[c0 + 1]) : 0.f;
        float b2 = (c0 + 2 < 27) ? __ldg(&pgb[c0 + 2]) : 0.f;
        float b3 = (c0 + 3 < 27) ? __ldg(&pgb[c0 + 3]) : 0.f;
        a00 = b0; a01 = b0; a10 = b1; a11 = b1;
        a20 = b2; a21 = b2; a30 = b3; a31 = b3;
    }
    const float* xb = &g_xT[(size_t)b * HH * WW * CC];

#pragma unroll 1
    for (int kk = 0; kk < NKK; kk++) {
        int dh = kk / 3 - 1, dw = kk % 3 - 1;
        int hh = h + dh;
        __syncthreads();
        // stage patch: 64 px x 64 c (float4 over c)
#pragma unroll
        for (int it = 0; it < 4; it++) {
            int idx = it * 256 + t;            // 0..1023
            int pix = idx >> 4;
            int c4  = idx & 15;
            int gw = wb + pix + dw;
            float4 v = make_float4(0.f, 0.f, 0.f, 0.f);
            if (hh >= 0 && hh < HH && gw >= 0 && gw < WW)
                v = __ldg((const float4*)&xb[((size_t)hh * WW + gw) * CC + c4 * 4]);
            *(float4*)&sp[pix * SPP + c4 * 4] = v;
        }
        // stage weights: 64 c x 32 co
#pragma unroll
        for (int it = 0; it < 2; it++) {
            int idx = it * 256 + t;            // 0..511
            ((float4*)swp)[idx] = __ldg(&((const float4*)g_wpg2)[kk * 512 + idx]);
        }
        __syncthreads();
        // GEMM over 64 channels
#pragma unroll 8
        for (int ql = 0; ql < 64; ql++) {
            float4 wv = *(const float4*)&swp[ql * 32 + og * 4];
            float s0 = sp[(pg * 2 + 0) * SPP + ql];
            float s1 = sp[(pg * 2 + 1) * SPP + ql];
            a00 += wv.x * s0; a01 += wv.x * s1;
            a10 += wv.y * s0; a11 += wv.y * s1;
            a20 += wv.z * s0; a21 += wv.z * s1;
            a30 += wv.w * s0; a31 += wv.w * s1;
        }
    }
    int w0 = wb + pg * 2;
    int c0 = og * 4;
    float* p0 = &g_params[((size_t)bh * WW + w0) * 27];
    float* p1 = p0 + 27;
    if (c0 + 0 < 27) { p0[c0 + 0] = a00; p1[c0 + 0] = a01; }
    if (c0 + 1 < 27) { p0[c0 + 1] = a10; p1[c0 + 1] = a11; }
    if (c0 + 2 < 27) { p0[c0 + 2] = a20; p1[c0 + 2] = a21; }
    if (c0 + 3 < 27) { p0[c0 + 3] = a30; p1[c0 + 3] = a31; }
}

// ============================================================
// Kernel 3: fused bilinear gather + GEMM, chunked over taps
// block = 64 px, 256 threads; weights staged in shared per tap
// ============================================================
__global__ void k_main(const float* __restrict__ bias,
                       float* __restrict__ out) {
    extern __shared__ float sm[];
    float* s  = sm;                      // [64][SP] sampled chunk
    float* sw = sm + 64 * SP;            // [64][64] weight chunk
    float* pw = sw + 64 * 64;            // [4][576]
    int*   pi = (int*)(pw + 4 * NPAIR);  // [4][576]

    int t = threadIdx.x;
    int blk = blockIdx.x;
    int wb = (blk & 1) * PIXB;
    int bh = blk >> 1;
    int b = bh >> 7, h = bh & 127;

    // ---- phase A: sampling params ----
    for (int pair = t; pair < NPAIR; pair += 256) {
        int kk  = pair >> 6;
        int pix = pair & 63;
        int w = wb + pix;
        const float* pp = &g_params[((size_t)bh * WW + w) * 27];
        float dy = pp[2 * kk];
        float dx = pp[2 * kk + 1];
        float m  = pp[18 + kk];
        float mask = 1.f / (1.f + expf(-m));
        float ys = (float)(h - 1 + kk / 3) + dy;
        float xs = (float)(w - 1 + kk % 3) + dx;
        float y0f = floorf(ys), x0f = floorf(xs);
        float ly = ys - y0f, lx = xs - x0f;
        int y0 = (int)y0f, x0 = (int)x0f;
        float vy0 = (y0 >= 0 && y0 < HH) ? 1.f : 0.f;
        float vy1 = (y0 + 1 >= 0 && y0 + 1 < HH) ? 1.f : 0.f;
        float vx0 = (x0 >= 0 && x0 < WW) ? 1.f : 0.f;
        float vx1 = (x0 + 1 >= 0 && x0 + 1 < WW) ? 1.f : 0.f;
        pw[0 * NPAIR + pair] = (1.f - ly) * (1.f - lx) * mask * vy0 * vx0;
        pw[1 * NPAIR + pair] = (1.f - ly) * lx         * mask * vy0 * vx1;
        pw[2 * NPAIR + pair] = ly * (1.f - lx)         * mask * vy1 * vx0;
        pw[3 * NPAIR + pair] = ly * lx                 * mask * vy1 * vx1;
        pi[0 * NPAIR + pair] = min(max(y0, 0), HH - 1) * WW;
        pi[1 * NPAIR + pair] = min(max(y0 + 1, 0), HH - 1) * WW;
        pi[2 * NPAIR + pair] = min(max(x0, 0), WW - 1);
        pi[3 * NPAIR + pair] = min(max(x0 + 1, 0), WW - 1);
    }

    int og = t & 15;                     // o = og*4..og*4+3
    int pg = t >> 4;                     // pixels pg*4..pg*4+3
    float acc[16];
    {
        float4 bv = __ldg(&((const float4*)bias)[og]);
#pragma unroll
        for (int p = 0; p < 4; p++) {
            acc[p * 4 + 0] = bv.x; acc[p * 4 + 1] = bv.y;
            acc[p * 4 + 2] = bv.z; acc[p * 4 + 3] = bv.w;
        }
    }
    const float* srow = &s[pg * 4];
    const float* xb = &g_xT[(size_t)b * HH * WW * CC];

#pragma unroll 1
    for (int kk = 0; kk < NKK; kk++) {
        __syncthreads();
        // ---- gather chunk: 64 c x 64 pix ----
#pragma unroll
        for (int it = 0; it < 16; it++) {
            int idx = it * 256 + t;
            int pix = idx >> 6;
            int c   = idx & 63;
            int pair = kk * 64 + pix;
            int r0 = pi[0 * NPAIR + pair];
            int r1 = pi[1 * NPAIR + pair];
            int x0c = pi[2 * NPAIR + pair];
            int x1c = pi[3 * NPAIR + pair];
            float w00 = pw[0 * NPAIR + pair];
            float w01 = pw[1 * NPAIR + pair];
            float w10 = pw[2 * NPAIR + pair];
            float w11 = pw[3 * NPAIR + pair];
            float v;
            v  = w00 * __ldg(&xb[(size_t)(r0 + x0c) * CC + c]);
            v += w01 * __ldg(&xb[(size_t)(r0 + x1c) * CC + c]);
            v += w10 * __ldg(&xb[(size_t)(r1 + x0c) * CC + c]);
            v += w11 * __ldg(&xb[(size_t)(r1 + x1c) * CC + c]);
            s[c * SP + pix] = v;
        }
        // ---- stage weight chunk: 64 q x 64 o ----
#pragma unroll
        for (int it = 0; it < 4; it++) {
            int idx = it * 256 + t;            // 0..1023 (float4)
            ((float4*)sw)[idx] = __ldg(&((const float4*)g_wT)[kk * 1024 + idx]);
        }
        __syncthreads();
        // ---- GEMM chunk ----
#pragma unroll 8
        for (int ql = 0; ql < 64; ql++) {
            float4 wv = *(const float4*)&sw[ql * 64 + og * 4];
            float s0 = srow[ql * SP];
            float s1 = srow[ql * SP + 1];
            float s2v = srow[ql * SP + 2];
            float s3 = srow[ql * SP + 3];
            acc[0]  += wv.x * s0;  acc[1]  += wv.y * s0;
            acc[2]  += wv.z * s0;  acc[3]  += wv.w * s0;
            acc[4]  += wv.x * s1;  acc[5]  += wv.y * s1;
            acc[6]  += wv.z * s1;  acc[7]  += wv.w * s1;
            acc[8]  += wv.x * s2v; acc[9]  += wv.y * s2v;
            acc[10] += wv.z * s2v; acc[11] += wv.w * s2v;
            acc[12] += wv.x * s3;  acc[13] += wv.y * s3;
            acc[14] += wv.z * s3;  acc[15] += wv.w * s3;
        }
    }

    int w0 = wb + pg * 4;
    size_t base = ((size_t)(b * OO + og * 4) * HH + h) * WW + w0;
    size_t ostride = (size_t)HH * WW;
#pragma unroll
    for (int i = 0; i < 4; i++) {
        float4 v;
        v.x = acc[0 * 4 + i]; v.y = acc[1 * 4 + i];
        v.z = acc[2 * 4 + i]; v.w = acc[3 * 4 + i];
        *(float4*)&out[base + i * ostride] = v;
    }
}

// ============================================================
extern "C" void kernel_launch(void* const* d_in, const int* in_sizes, int n_in,
                              void* d_out, int out_size) {
    const float* x      = (const float*)d_in[0];
    const float* weight = (const float*)d_in[1];
    const float* bias   = (const float*)d_in[2];
    const float* pg_w   = (const float*)d_in[3];
    const float* pg_b   = (const float*)d_in[4];
    float* out = (float*)d_out;

    const int SMEM_MAIN = (64 * SP + 64 * 64 + 8 * NPAIR) * 4;   // ~51.4 KB

    cudaFuncSetAttribute(k_main, cudaFuncAttributeMaxDynamicSharedMemorySize, SMEM_MAIN);

    k_transpose_x<<<BB * HH, 256>>>(x);
    k_transpose_w<<<(OO * CC * NKK + 255) / 256, 256>>>(weight);
    k_prep_wpg2<<<(NKK * CC * 32 + 255) / 256, 256>>>(pg_w);
    k_params<<<BB * HH * (WW / PIXB), 256>>>(pg_b);
    k_main<<<BB * HH * (WW / PIXB), 256, SMEM_MAIN>>>(bias, out);
}